// round 10
// baseline (speedup 1.0000x reference)
#include <cuda_runtime.h>
#include <cuda_fp16.h>
#include <cstdint>

#define NTHREADS 128

// Fused packed-fp16 |x-w| accumulate. Weight operand is pre-negated, so the
// first add is the subtraction. abs of both halves = ONE 32-bit AND.
__device__ __forceinline__ void fused_h(uint32_t &acc, uint32_t xv, uint32_t wv){
    asm("{\n\t"
        ".reg .b32 t;\n\t"
        "add.rn.f16x2 t, %1, %2;\n\t"
        "and.b32 t, t, 0x7FFF7FFF;\n\t"
        "add.rn.f16x2 %0, %0, t;\n\t"
        "}\n" : "+r"(acc) : "r"(xv), "r"(wv));
}

// duplicated (v,v) half2 from one f32
__device__ __forceinline__ uint32_t f2dup(float v){
    uint32_t d;
    asm("cvt.rn.f16x2.f32 %0, %1, %1;" : "=r"(d) : "f"(v));
    return d;
}
// pack (lo,hi) floats into half2 with lo in low 16 bits
__device__ __forceinline__ uint32_t packh2(float lo, float hi){
    uint32_t d;
    asm("cvt.rn.f16x2.f32 %0, %1, %2;" : "=r"(d) : "f"(hi), "f"(lo));
    return d;
}
// unpack half2 into two f32
__device__ __forceinline__ void unpackh2(uint32_t h, float &lo, float &hi){
    asm("{\n\t.reg .b16 l, u;\n\tmov.b32 {l, u}, %2;\n\t"
        "cvt.f32.f16 %0, l;\n\tcvt.f32.f16 %1, u;\n\t}"
        : "=f"(lo), "=f"(hi) : "r"(h));
}

__device__ __forceinline__ void cpasync16(uint32_t daddr, const float* g, int srcsize){
    asm volatile("cp.async.cg.shared.global [%0], [%1], 16, %2;"
                 :: "r"(daddr), "l"(g), "r"(srcsize));
}
__device__ __forceinline__ void cp_commit(){ asm volatile("cp.async.commit_group;"); }
template<int N> __device__ __forceinline__ void cp_wait(){
    asm volatile("cp.async.wait_group %0;" :: "n"(N));
}

// Stripe tile: 64 wide x 4 tall, 4 output channels per CTA, channels chunked by 4.
// smem x tile row = 72 u32 cells. After conversion each cell holds a DUPLICATED
// half2 (v,v). Data cells idx 4..67 = cols 0..63 (cp.async 16B-aligned there).
// The +/-1 column neighbors needed by the 3x3 window come from warp shuffles:
// lane jp's left neighbor cell == lane jp-1's right cell; edge lanes use the
// true zero image padding (stripes are full image width).
#define ROWU 72
#define CHU  (6 * ROWU)      // 6 rows (4 + halo) per channel
#define BUFU (4 * CHU)       // 4 channels per chunk = 1728 cells

__global__ __launch_bounds__(NTHREADS, 10)
void adder_kernel(const float* __restrict__ x,
                  const float* __restrict__ w,
                  const float* __restrict__ alpha,
                  float* __restrict__ out)
{
    __shared__ __align__(16) uint32_t s_xh[2 * BUFU];     // 13.8 KB double-buffered
    __shared__ __align__(16) uint32_t s_w2h[64 * 9 * 2];  // negated o-pair half2 weights 4.6 KB

    const int tid  = threadIdx.x;
    const int bx   = blockIdx.x;
    const int b    = bx >> 8;          // 8 batches
    const int st   = (bx >> 4) & 15;   // 16 row-stripes of 4
    const int ob   = bx & 15;          // 16 o-blocks of 4 (fastest: x L2 reuse)
    const int rloc = tid >> 5;         // 0..3 output row in stripe (one row per warp)
    const int jp   = tid & 31;         // pair index; pixels j0=2jp, j0+1
    const int R0   = st * 4;

    const uint32_t sbase = (uint32_t)__cvta_generic_to_shared(s_xh);

    // per-thread unit decomposition for loads/converts: 3 units of 16 B each
    int u_ci[3], u_r[3], u_q[3];
    #pragma unroll
    for (int k = 0; k < 3; ++k) {
        int u = tid + k * NTHREADS;                // 0..383
        u_ci[k] = u / 96;
        int rem = u - u_ci[k] * 96;
        u_r[k] = rem >> 4;
        u_q[k] = rem & 15;
    }

    // ---- kick off chunk 0 loads ASAP ----
    #pragma unroll
    for (int k = 0; k < 3; ++k) {
        int gi = R0 - 1 + u_r[k];
        const float* src = x + (((b * 64 + u_ci[k]) * 64 + gi) * 64) + u_q[k] * 4;
        uint32_t dst = sbase + ((u_ci[k] * 6 + u_r[k]) * ROWU + 4 + u_q[k] * 4) * 4;
        cpasync16(dst, src, ((unsigned)gi < 64u) ? 16 : 0);
    }
    cp_commit();

    // ---- stage negated, o-pair half2 weights: s_w2h[(c*9+tap)*2 + p] ----
    for (int e = tid; e < 64 * 9 * 2; e += NTHREADS) {
        int c   = e / 18;
        int r   = e - c * 18;
        int tap = r >> 1;
        int p   = r & 1;
        int o0  = ob * 4 + 2 * p;
        float lo = -w[(o0 * 64 + c) * 9 + tap];
        float hi = -w[((o0 + 1) * 64 + c) * 9 + tap];
        s_w2h[e] = packh2(lo, hi);
    }

    // fp32 master accumulators (merged once per chunk for precision)
    float accF[2][4];
    #pragma unroll
    for (int p = 0; p < 2; ++p)
        #pragma unroll
        for (int o = 0; o < 4; ++o) accF[p][o] = 0.0f;

    // ---- prologue: finish chunk 0 (convert own cells in place), bar, start chunk 1
    cp_wait<0>();
    #pragma unroll
    for (int k = 0; k < 3; ++k) {
        uint32_t* cell = s_xh + (u_ci[k] * 6 + u_r[k]) * ROWU + 4 + u_q[k] * 4;
        float4 v = *(float4*)cell;
        uint4 o;
        o.x = f2dup(v.x); o.y = f2dup(v.y); o.z = f2dup(v.z); o.w = f2dup(v.w);
        *(uint4*)cell = o;
    }
    __syncthreads();
    #pragma unroll
    for (int k = 0; k < 3; ++k) {
        int gi = R0 - 1 + u_r[k];
        const float* src = x + (((b * 64 + 4 + u_ci[k]) * 64 + gi) * 64) + u_q[k] * 4;
        uint32_t dst = sbase + (BUFU + (u_ci[k] * 6 + u_r[k]) * ROWU + 4 + u_q[k] * 4) * 4;
        cpasync16(dst, src, ((unsigned)gi < 64u) ? 16 : 0);
    }
    cp_commit();

    #pragma unroll 1
    for (int ck = 0; ck < 16; ++ck) {
        // half2 chunk accumulators: <=36 terms per half -> fp16-safe window
        uint32_t acch[2][2];
        acch[0][0] = acch[0][1] = acch[1][0] = acch[1][1] = 0u;

        // ---- compute 4 channels from buffer ck&1 (tile already dup-half2) ----
        const uint32_t* xb  = s_xh  + (ck & 1) * BUFU;
        const uint32_t* wcb = s_w2h + ck * 4 * 18;
        #pragma unroll 1
        for (int cc = 0; cc < 4; ++cc) {
            const uint32_t* wc = wcb + cc * 18;
            #pragma unroll
            for (int kh = 0; kh < 3; ++kh) {
                const uint32_t* xr = xb + cc * CHU + (rloc + kh) * ROWU;
                const uint2 B = *(const uint2*)(xr + 4 + 2 * jp);   // cells (j0, j0+1)
                uint32_t xh[4];
                xh[1] = B.x;
                xh[2] = B.y;
                // neighbors via warp shuffle; edge lanes = true zero image pad
                uint32_t l = __shfl_up_sync(0xFFFFFFFFu, B.y, 1);
                uint32_t r = __shfl_down_sync(0xFFFFFFFFu, B.x, 1);
                xh[0] = (jp == 0)  ? 0u : l;   // col j0-1
                xh[3] = (jp == 31) ? 0u : r;   // col j0+2
                #pragma unroll
                for (int kw = 0; kw < 3; ++kw) {
                    const uint2 wq = *(const uint2*)(wc + (kh * 3 + kw) * 2);  // 2 o-pairs
                    fused_h(acch[0][0], xh[kw],     wq.x);
                    fused_h(acch[1][0], xh[kw + 1], wq.x);
                    fused_h(acch[0][1], xh[kw],     wq.y);
                    fused_h(acch[1][1], xh[kw + 1], wq.y);
                }
            }
        }

        // ---- merge chunk (fp16) into fp32 master accumulators ----
        #pragma unroll
        for (int p = 0; p < 2; ++p)
            #pragma unroll
            for (int op = 0; op < 2; ++op) {
                float lo, hi;
                unpackh2(acch[p][op], lo, hi);
                accF[p][2 * op]     += lo;
                accF[p][2 * op + 1] += hi;
            }

        // ---- finish chunk ck+1: wait its loads, convert own cells in place ----
        if (ck < 15) {
            cp_wait<0>();
            uint32_t* bnext = s_xh + ((ck + 1) & 1) * BUFU;
            #pragma unroll
            for (int k = 0; k < 3; ++k) {
                uint32_t* cell = bnext + (u_ci[k] * 6 + u_r[k]) * ROWU + 4 + u_q[k] * 4;
                float4 v = *(float4*)cell;
                uint4 o;
                o.x = f2dup(v.x); o.y = f2dup(v.y); o.z = f2dup(v.z); o.w = f2dup(v.w);
                *(uint4*)cell = o;
            }
        }
        __syncthreads();   // chunk ck+1 converted everywhere; all readers of ck done

        // ---- start chunk ck+2 into the buffer just freed ----
        if (ck < 14) {
            #pragma unroll
            for (int k = 0; k < 3; ++k) {
                int gi = R0 - 1 + u_r[k];
                const float* src = x + (((b * 64 + (ck + 2) * 4 + u_ci[k]) * 64 + gi) * 64) + u_q[k] * 4;
                uint32_t dst = sbase + ((ck & 1) * BUFU + (u_ci[k] * 6 + u_r[k]) * ROWU + 4 + u_q[k] * 4) * 4;
                cpasync16(dst, src, ((unsigned)gi < 64u) ? 16 : 0);
            }
            cp_commit();
        }
    }

    // ---- epilogue: y = x - sum;  out = sign(y)*|y|^alpha (alpha==1 fast path) ----
    const float a = alpha[0];
    const int gi  = R0 + rloc;
    const int j0  = 2 * jp;
    const int base = ((b * 64 + ob * 4) * 64 + gi) * 64 + j0;

    #pragma unroll
    for (int o = 0; o < 4; ++o) {
        const float2 xv = *(const float2*)(x + base + o * 4096);
        float y0 = xv.x - accF[0][o];
        float y1 = xv.y - accF[1][o];
        float r0, r1;
        if (a == 1.0f) { r0 = y0; r1 = y1; }
        else {
            r0 = copysignf(powf(fabsf(y0), a), y0);
            r1 = copysignf(powf(fabsf(y1), a), y1);
        }
        *(float2*)(out + base + o * 4096) = make_float2(r0, r1);
    }
}

extern "C" void kernel_launch(void* const* d_in, const int* in_sizes, int n_in,
                              void* d_out, int out_size)
{
    (void)in_sizes; (void)n_in; (void)out_size;
    const float* x     = (const float*)d_in[0];
    const float* wgt   = (const float*)d_in[1];
    const float* alpha = (const float*)d_in[2];
    float* out = (float*)d_out;
    // grid: 8 batches * 16 row-stripes(64x4) * 16 o-blocks(4 outputs) = 2048 CTAs
    adder_kernel<<<2048, NTHREADS>>>(x, wgt, alpha, out);
}

// round 11
// speedup vs baseline: 1.1258x; 1.1258x over previous
#include <cuda_runtime.h>
#include <cuda_fp16.h>
#include <cstdint>

#define NTHREADS 128

// pack (lo,hi) floats into half2 with lo in low 16 bits
__device__ __forceinline__ uint32_t packh2(float lo, float hi){
    uint32_t d;
    asm("cvt.rn.f16x2.f32 %0, %1, %2;" : "=r"(d) : "f"(hi), "f"(lo));
    return d;
}
// duplicated (v,v) half2 from one f32
__device__ __forceinline__ __half2 f2dup(float v){
    uint32_t d;
    asm("cvt.rn.f16x2.f32 %0, %1, %1;" : "=r"(d) : "f"(v));
    return *reinterpret_cast<__half2*>(&d);
}

__device__ __forceinline__ void cpasync16(uint32_t daddr, const float* g, int srcsize){
    asm volatile("cp.async.cg.shared.global [%0], [%1], 16, %2;"
                 :: "r"(daddr), "l"(g), "r"(srcsize));
}
__device__ __forceinline__ void cp_commit(){ asm volatile("cp.async.commit_group;"); }
template<int N> __device__ __forceinline__ void cp_wait(){
    asm volatile("cp.async.wait_group %0;" :: "n"(N));
}

// Stripe tile: 64 wide x 4 tall, 8 output channels per CTA, channels chunked by 4.
// smem x row layout (scalar f32, 72 per row): idx 0..2 pad, idx 3 left-halo zero,
// idx 4..67 cols 0..63, idx 68 right-halo zero, idx 69..71 pad.
#define ROWF 72
#define CHF  (6 * ROWF)
#define BUFF (4 * CHF)

__global__ __launch_bounds__(NTHREADS, 7)
void adder_kernel(const float* __restrict__ x,
                  const float* __restrict__ w,
                  const float* __restrict__ alpha,
                  float* __restrict__ out)
{
    __shared__ __align__(16) float    s_xf[2 * BUFF];     // 13.8 KB double-buffered
    __shared__ __align__(16) uint32_t s_w2h[64 * 9 * 4];  // POSITIVE o-pair half2 weights 9.2 KB

    const int tid  = threadIdx.x;
    const int bx   = blockIdx.x;
    const int b    = bx >> 7;          // 8 batches
    const int st   = (bx >> 3) & 15;   // 16 row-stripes of 4
    const int ob   = bx & 7;           // 8 o-blocks (fastest: x L2 reuse)
    const int rloc = tid >> 5;         // 0..3 output row in stripe
    const int jp   = tid & 31;         // pair index; pixels j0=2jp, j0+1
    const int R0   = st * 4;

    const uint32_t sbase = (uint32_t)__cvta_generic_to_shared(s_xf);

    // ---- kick off chunk 0 loads ASAP ----
    {
        #pragma unroll
        for (int k = 0; k < 3; ++k) {
            int u = tid + k * NTHREADS;                // 0..383
            int ci = u / 96, rem = u - ci * 96;
            int r = rem >> 4, q = rem & 15;
            int gi = R0 - 1 + r;
            const float* src = x + (((b * 64 + ci) * 64 + gi) * 64) + q * 4;
            uint32_t dst = sbase + ((ci * 6 + r) * ROWF + 4 + q * 4) * 4;
            cpasync16(dst, src, ((unsigned)gi < 64u) ? 16 : 0);
        }
        cp_commit();
    }

    // ---- persistent halo-zero pads (never overwritten by cp.async) ----
    for (int u = tid; u < 96; u += NTHREADS) {
        int side = u & 1, rr = u >> 1;       // 48 rows total (2 bufs * 24 rows)
        int buf = rr / 24, rem = rr - buf * 24;
        s_xf[buf * BUFF + rem * ROWF + (side ? 68 : 3)] = 0.0f;
    }

    // ---- stage POSITIVE o-pair half2 weights: s_w2h[(c*9+tap)*4 + opair] ----
    for (int e = tid; e < 64 * 9 * 4; e += NTHREADS) {
        int c   = e / 36;
        int r   = e - c * 36;
        int tap = r >> 2;
        int p   = r & 3;
        int o0  = ob * 8 + 2 * p;
        float lo = w[(o0 * 64 + c) * 9 + tap];
        float hi = w[((o0 + 1) * 64 + c) * 9 + tap];
        s_w2h[e] = packh2(lo, hi);
    }

    // fp32 master accumulators (merged once per chunk for precision)
    float accF[2][8];
    #pragma unroll
    for (int p = 0; p < 2; ++p)
        #pragma unroll
        for (int o = 0; o < 8; ++o) accF[p][o] = 0.0f;

    const int xoff = 2 + 2 * jp;   // even f32 idx; window covers cols j0-1..j0+2

    #pragma unroll 1
    for (int ck = 0; ck < 16; ++ck) {
        // prefetch next chunk into the other buffer
        if (ck < 15) {
            #pragma unroll
            for (int k = 0; k < 3; ++k) {
                int u = tid + k * NTHREADS;
                int ci = u / 96, rem = u - ci * 96;
                int r = rem >> 4, q = rem & 15;
                int gi = R0 - 1 + r;
                const float* src = x + (((b * 64 + (ck + 1) * 4 + ci) * 64 + gi) * 64) + q * 4;
                uint32_t dst = sbase + (((ck + 1) & 1) * BUFF + (ci * 6 + r) * ROWF + 4 + q * 4) * 4;
                cpasync16(dst, src, ((unsigned)gi < 64u) ? 16 : 0);
            }
            cp_commit();
            cp_wait<1>();     // current chunk's group done
        } else {
            cp_wait<0>();
        }
        __syncthreads();      // chunk ck visible to all warps

        // half2 chunk accumulators: <=36 terms per half -> fp16-safe window
        __half2 acch[2][4];
        #pragma unroll
        for (int p = 0; p < 2; ++p)
            #pragma unroll
            for (int op = 0; op < 4; ++op) acch[p][op] = __half2half2(__ushort_as_half(0));

        // ---- compute 4 channels from buffer ck&1 ----
        const float*     xb  = s_xf  + (ck & 1) * BUFF;
        const uint32_t*  wcb = s_w2h + ck * 4 * 36;
        #pragma unroll 1
        for (int cc = 0; cc < 4; ++cc) {
            const uint32_t* wc = wcb + cc * 36;
            #pragma unroll
            for (int kh = 0; kh < 3; ++kh) {
                const float* p0 = xb + (cc * 6 + rloc + kh) * ROWF + xoff;
                const float2 A = *(const float2*)(p0);      // (pad/x, col j0-1)
                const float2 B = *(const float2*)(p0 + 2);  // (col j0, col j0+1)
                const float2 C = *(const float2*)(p0 + 4);  // (col j0+2, pad/x)
                __half2 xh[4];
                xh[0] = f2dup(A.y);
                xh[1] = f2dup(B.x);
                xh[2] = f2dup(B.y);
                xh[3] = f2dup(C.x);
                #pragma unroll
                for (int kw = 0; kw < 3; ++kw) {
                    uint4 wq = *(const uint4*)(wc + (kh * 3 + kw) * 4);  // 4 o-pairs
                    const __half2 w0 = *reinterpret_cast<__half2*>(&wq.x);
                    const __half2 w1 = *reinterpret_cast<__half2*>(&wq.y);
                    const __half2 w2 = *reinterpret_cast<__half2*>(&wq.z);
                    const __half2 w3 = *reinterpret_cast<__half2*>(&wq.w);
                    // core: acc += |x - w|.  Intrinsic form lets ptxas fold the
                    // abs/neg into HADD2 source modifiers (FADD-style |src|).
                    acch[0][0] = __hadd2(acch[0][0], __habs2(__hsub2(xh[kw],     w0)));
                    acch[1][0] = __hadd2(acch[1][0], __habs2(__hsub2(xh[kw + 1], w0)));
                    acch[0][1] = __hadd2(acch[0][1], __habs2(__hsub2(xh[kw],     w1)));
                    acch[1][1] = __hadd2(acch[1][1], __habs2(__hsub2(xh[kw + 1], w1)));
                    acch[0][2] = __hadd2(acch[0][2], __habs2(__hsub2(xh[kw],     w2)));
                    acch[1][2] = __hadd2(acch[1][2], __habs2(__hsub2(xh[kw + 1], w2)));
                    acch[0][3] = __hadd2(acch[0][3], __habs2(__hsub2(xh[kw],     w3)));
                    acch[1][3] = __hadd2(acch[1][3], __habs2(__hsub2(xh[kw + 1], w3)));
                }
            }
        }

        // ---- merge chunk (fp16) into fp32 master accumulators ----
        #pragma unroll
        for (int p = 0; p < 2; ++p)
            #pragma unroll
            for (int op = 0; op < 4; ++op) {
                accF[p][2 * op]     += __low2float(acch[p][op]);
                accF[p][2 * op + 1] += __high2float(acch[p][op]);
            }

        __syncthreads();      // all reads of buf ck&1 done before it is refilled
    }

    // ---- epilogue: y = x - sum;  out = sign(y)*|y|^alpha (alpha==1 fast path) ----
    const float a = alpha[0];
    const int gi  = R0 + rloc;
    const int j0  = 2 * jp;
    const int base = ((b * 64 + ob * 8) * 64 + gi) * 64 + j0;

    #pragma unroll
    for (int o = 0; o < 8; ++o) {
        const float2 xv = *(const float2*)(x + base + o * 4096);
        float y0 = xv.x - accF[0][o];
        float y1 = xv.y - accF[1][o];
        float r0, r1;
        if (a == 1.0f) { r0 = y0; r1 = y1; }
        else {
            r0 = copysignf(powf(fabsf(y0), a), y0);
            r1 = copysignf(powf(fabsf(y1), a), y1);
        }
        *(float2*)(out + base + o * 4096) = make_float2(r0, r1);
    }
}

extern "C" void kernel_launch(void* const* d_in, const int* in_sizes, int n_in,
                              void* d_out, int out_size)
{
    (void)in_sizes; (void)n_in; (void)out_size;
    const float* x     = (const float*)d_in[0];
    const float* wgt   = (const float*)d_in[1];
    const float* alpha = (const float*)d_in[2];
    float* out = (float*)d_out;
    // grid: 8 batches * 16 row-stripes(64x4) * 8 o-blocks = 1024 CTAs
    adder_kernel<<<1024, NTHREADS>>>(x, wgt, alpha, out);
}

// round 12
// speedup vs baseline: 1.1573x; 1.0280x over previous
#include <cuda_runtime.h>
#include <cuda_fp16.h>
#include <cstdint>

#define NTHREADS 128

// pack (lo,hi) floats into half2 with lo in low 16 bits
__device__ __forceinline__ uint32_t packh2(float lo, float hi){
    uint32_t d;
    asm("cvt.rn.f16x2.f32 %0, %1, %2;" : "=r"(d) : "f"(hi), "f"(lo));
    return d;
}
// duplicated (v,v) half2 bits from one f32
__device__ __forceinline__ uint32_t f2dup(float v){
    uint32_t d;
    asm("cvt.rn.f16x2.f32 %0, %1, %1;" : "=r"(d) : "f"(v));
    return d;
}

__device__ __forceinline__ void cpasync16(uint32_t daddr, const float* g, int srcsize){
    asm volatile("cp.async.cg.shared.global [%0], [%1], 16, %2;"
                 :: "r"(daddr), "l"(g), "r"(srcsize));
}
__device__ __forceinline__ void cp_commit(){ asm volatile("cp.async.commit_group;"); }
template<int N> __device__ __forceinline__ void cp_wait(){
    asm volatile("cp.async.wait_group %0;" :: "n"(N));
}

// Stripe tile: 64 wide x 4 tall, 8 output channels per CTA, channels chunked by 4.
// smem x tile row = 72 u32 cells. After the in-place convert pass each cell holds
// a DUPLICATED half2 (v,v). Layout: idx 0..2 pad, idx 3 left-halo zero,
// idx 4..67 cols 0..63, idx 68 right-halo zero, idx 69..71 pad.
// cp.async lands raw f32 in idx 4..67; each thread then converts exactly the
// 16B blocks it copied (no extra barrier needed before the conversion).
#define ROWU 72
#define CHU  (6 * ROWU)      // 6 rows (4 + halo) per channel
#define BUFU (4 * CHU)       // 4 channels per chunk = 1728 cells

__global__ __launch_bounds__(NTHREADS, 8)
void adder_kernel(const float* __restrict__ x,
                  const float* __restrict__ w,
                  const float* __restrict__ alpha,
                  float* __restrict__ out)
{
    __shared__ __align__(16) uint32_t s_xh[2 * BUFU];     // 13.8 KB double-buffered
    __shared__ __align__(16) uint32_t s_w2h[64 * 9 * 4];  // POSITIVE o-pair half2 weights 9.2 KB

    const int tid  = threadIdx.x;
    const int bx   = blockIdx.x;
    const int b    = bx >> 7;          // 8 batches
    const int st   = (bx >> 3) & 15;   // 16 row-stripes of 4
    const int ob   = bx & 7;           // 8 o-blocks (fastest: x L2 reuse)
    const int rloc = tid >> 5;         // 0..3 output row in stripe (one row per warp)
    const int jp   = tid & 31;         // pair index; pixels j0=2jp, j0+1
    const int R0   = st * 4;

    const uint32_t sbase = (uint32_t)__cvta_generic_to_shared(s_xh);

    // per-thread unit decomposition for loads/converts: 3 units of 16 B each
    int u_ci[3], u_r[3], u_q[3];
    #pragma unroll
    for (int k = 0; k < 3; ++k) {
        int u = tid + k * NTHREADS;                // 0..383
        u_ci[k] = u / 96;
        int rem = u - u_ci[k] * 96;
        u_r[k] = rem >> 4;
        u_q[k] = rem & 15;
    }

    // ---- kick off chunk 0 loads ASAP ----
    #pragma unroll
    for (int k = 0; k < 3; ++k) {
        int gi = R0 - 1 + u_r[k];
        const float* src = x + (((b * 64 + u_ci[k]) * 64 + gi) * 64) + u_q[k] * 4;
        uint32_t dst = sbase + ((u_ci[k] * 6 + u_r[k]) * ROWU + 4 + u_q[k] * 4) * 4;
        cpasync16(dst, src, ((unsigned)gi < 64u) ? 16 : 0);
    }
    cp_commit();

    // ---- persistent halo-zero pads (dup-h2 zero == 0u; never overwritten) ----
    for (int u = tid; u < 96; u += NTHREADS) {
        int side = u & 1, rr = u >> 1;       // 48 rows (2 bufs * 24 ch-rows)
        int buf = rr / 24, rem = rr - buf * 24;
        s_xh[buf * BUFU + rem * ROWU + (side ? 68 : 3)] = 0u;
    }

    // ---- stage POSITIVE o-pair half2 weights: s_w2h[(c*9+tap)*4 + opair] ----
    for (int e = tid; e < 64 * 9 * 4; e += NTHREADS) {
        int c   = e / 36;
        int r   = e - c * 36;
        int tap = r >> 2;
        int p   = r & 3;
        int o0  = ob * 8 + 2 * p;
        float lo = w[(o0 * 64 + c) * 9 + tap];
        float hi = w[((o0 + 1) * 64 + c) * 9 + tap];
        s_w2h[e] = packh2(lo, hi);
    }

    // fp32 master accumulators (merged once per chunk for precision)
    float accF[2][8];
    #pragma unroll
    for (int p = 0; p < 2; ++p)
        #pragma unroll
        for (int o = 0; o < 8; ++o) accF[p][o] = 0.0f;

    // ---- prologue: finish chunk 0 (convert own cells in place), bar, start chunk 1
    cp_wait<0>();
    #pragma unroll
    for (int k = 0; k < 3; ++k) {
        uint32_t* cell = s_xh + (u_ci[k] * 6 + u_r[k]) * ROWU + 4 + u_q[k] * 4;
        float4 v = *(float4*)cell;
        uint4 o;
        o.x = f2dup(v.x); o.y = f2dup(v.y); o.z = f2dup(v.z); o.w = f2dup(v.w);
        *(uint4*)cell = o;
    }
    __syncthreads();
    #pragma unroll
    for (int k = 0; k < 3; ++k) {
        int gi = R0 - 1 + u_r[k];
        const float* src = x + (((b * 64 + 4 + u_ci[k]) * 64 + gi) * 64) + u_q[k] * 4;
        uint32_t dst = sbase + (BUFU + (u_ci[k] * 6 + u_r[k]) * ROWU + 4 + u_q[k] * 4) * 4;
        cpasync16(dst, src, ((unsigned)gi < 64u) ? 16 : 0);
    }
    cp_commit();

    #pragma unroll 1
    for (int ck = 0; ck < 16; ++ck) {
        // half2 chunk accumulators: <=36 terms per half -> fp16-safe window
        __half2 acch[2][4];
        #pragma unroll
        for (int p = 0; p < 2; ++p)
            #pragma unroll
            for (int op = 0; op < 4; ++op) acch[p][op] = __half2half2(__ushort_as_half(0));

        // ---- compute 4 channels from buffer ck&1 (tile already dup-half2) ----
        const uint32_t* xb  = s_xh  + (ck & 1) * BUFU;
        const uint32_t* wcb = s_w2h + ck * 4 * 36;
        #pragma unroll 1
        for (int cc = 0; cc < 4; ++cc) {
            const uint32_t* wc = wcb + cc * 36;
            #pragma unroll
            for (int kh = 0; kh < 3; ++kh) {
                const uint32_t* xr = xb + cc * CHU + (rloc + kh) * ROWU;
                const uint2 A = *(const uint2*)(xr + 2 + 2 * jp);   // (col j0-2, col j0-1)
                const uint2 B = *(const uint2*)(xr + 4 + 2 * jp);   // (col j0,   col j0+1)
                const uint32_t Cc = xr[6 + 2 * jp];                 //  col j0+2
                uint32_t xb0 = A.y, xb1 = B.x, xb2 = B.y, xb3 = Cc;
                __half2 xh[4];
                xh[0] = *reinterpret_cast<__half2*>(&xb0);
                xh[1] = *reinterpret_cast<__half2*>(&xb1);
                xh[2] = *reinterpret_cast<__half2*>(&xb2);
                xh[3] = *reinterpret_cast<__half2*>(&xb3);
                #pragma unroll
                for (int kw = 0; kw < 3; ++kw) {
                    uint4 wq = *(const uint4*)(wc + (kh * 3 + kw) * 4);  // 4 o-pairs
                    const __half2 w0 = *reinterpret_cast<__half2*>(&wq.x);
                    const __half2 w1 = *reinterpret_cast<__half2*>(&wq.y);
                    const __half2 w2 = *reinterpret_cast<__half2*>(&wq.z);
                    const __half2 w3 = *reinterpret_cast<__half2*>(&wq.w);
                    // core: acc += |x - w| ; abs/neg fold into HADD2 src modifiers
                    acch[0][0] = __hadd2(acch[0][0], __habs2(__hsub2(xh[kw],     w0)));
                    acch[1][0] = __hadd2(acch[1][0], __habs2(__hsub2(xh[kw + 1], w0)));
                    acch[0][1] = __hadd2(acch[0][1], __habs2(__hsub2(xh[kw],     w1)));
                    acch[1][1] = __hadd2(acch[1][1], __habs2(__hsub2(xh[kw + 1], w1)));
                    acch[0][2] = __hadd2(acch[0][2], __habs2(__hsub2(xh[kw],     w2)));
                    acch[1][2] = __hadd2(acch[1][2], __habs2(__hsub2(xh[kw + 1], w2)));
                    acch[0][3] = __hadd2(acch[0][3], __habs2(__hsub2(xh[kw],     w3)));
                    acch[1][3] = __hadd2(acch[1][3], __habs2(__hsub2(xh[kw + 1], w3)));
                }
            }
        }

        // ---- merge chunk (fp16) into fp32 master accumulators ----
        #pragma unroll
        for (int p = 0; p < 2; ++p)
            #pragma unroll
            for (int op = 0; op < 4; ++op) {
                accF[p][2 * op]     += __low2float(acch[p][op]);
                accF[p][2 * op + 1] += __high2float(acch[p][op]);
            }

        // ---- finish chunk ck+1: wait its loads, convert own cells in place ----
        if (ck < 15) {
            cp_wait<0>();
            uint32_t* bnext = s_xh + ((ck + 1) & 1) * BUFU;
            #pragma unroll
            for (int k = 0; k < 3; ++k) {
                uint32_t* cell = bnext + (u_ci[k] * 6 + u_r[k]) * ROWU + 4 + u_q[k] * 4;
                float4 v = *(float4*)cell;
                uint4 o;
                o.x = f2dup(v.x); o.y = f2dup(v.y); o.z = f2dup(v.z); o.w = f2dup(v.w);
                *(uint4*)cell = o;
            }
        }
        __syncthreads();   // chunk ck+1 converted everywhere; all readers of ck done

        // ---- start chunk ck+2 into the buffer just freed ----
        if (ck < 14) {
            #pragma unroll
            for (int k = 0; k < 3; ++k) {
                int gi = R0 - 1 + u_r[k];
                const float* src = x + (((b * 64 + (ck + 2) * 4 + u_ci[k]) * 64 + gi) * 64) + u_q[k] * 4;
                uint32_t dst = sbase + ((ck & 1) * BUFU + (u_ci[k] * 6 + u_r[k]) * ROWU + 4 + u_q[k] * 4) * 4;
                cpasync16(dst, src, ((unsigned)gi < 64u) ? 16 : 0);
            }
            cp_commit();
        }
    }

    // ---- epilogue: y = x - sum;  out = sign(y)*|y|^alpha (alpha==1 fast path) ----
    const float a = alpha[0];
    const int gi  = R0 + rloc;
    const int j0  = 2 * jp;
    const int base = ((b * 64 + ob * 8) * 64 + gi) * 64 + j0;

    #pragma unroll
    for (int o = 0; o < 8; ++o) {
        const float2 xv = *(const float2*)(x + base + o * 4096);
        float y0 = xv.x - accF[0][o];
        float y1 = xv.y - accF[1][o];
        float r0, r1;
        if (a == 1.0f) { r0 = y0; r1 = y1; }
        else {
            r0 = copysignf(powf(fabsf(y0), a), y0);
            r1 = copysignf(powf(fabsf(y1), a), y1);
        }
        *(float2*)(out + base + o * 4096) = make_float2(r0, r1);
    }
}

extern "C" void kernel_launch(void* const* d_in, const int* in_sizes, int n_in,
                              void* d_out, int out_size)
{
    (void)in_sizes; (void)n_in; (void)out_size;
    const float* x     = (const float*)d_in[0];
    const float* wgt   = (const float*)d_in[1];
    const float* alpha = (const float*)d_in[2];
    float* out = (float*)d_out;
    // grid: 8 batches * 16 row-stripes(64x4) * 8 o-blocks = 1024 CTAs
    adder_kernel<<<1024, NTHREADS>>>(x, wgt, alpha, out);
}